// round 5
// baseline (speedup 1.0000x reference)
#include <cuda_runtime.h>
#include <math.h>

#define NB   4096   // batch
#define LD   68     // padded row stride (floats) for 64-wide matrices
#define LDF  132    // padded row stride for FFN hidden (128-wide)

typedef unsigned long long ull;

__device__ __forceinline__ ull pack2(float x, float y) {
    ull r; asm("mov.b64 %0, {%1, %2};" : "=l"(r) : "f"(x), "f"(y)); return r;
}
__device__ __forceinline__ float2 unpack2(ull v) {
    float2 r; asm("mov.b64 {%0, %1}, %2;" : "=f"(r.x), "=f"(r.y) : "l"(v)); return r;
}
__device__ __forceinline__ ull ffma2(ull a, ull b, ull c) {
    ull r; asm("fma.rn.f32x2 %0, %1, %2, %3;" : "=l"(r) : "l"(a), "l"(b), "l"(c)); return r;
}
__device__ __forceinline__ float ex2f(float x) {
    float r; asm("ex2.approx.f32 %0, %1;" : "=f"(r) : "f"(x)); return r;
}
__device__ __forceinline__ float lg2f_(float x) {
    float r; asm("lg2.approx.f32 %0, %1;" : "=f"(r) : "f"(x)); return r;
}

#define LOG2E    1.4426950408889634f
#define LOG2_10  3.3219280948873623f
#define SGRP     (0.125f * LOG2E)
#define SATT     (0.25f  * LOG2E)

// ---------------- packed-weight scratch (k-interleaved pairs) ----------------
#define WP_GRPQ 0
#define WP_GRPK 8192
#define WP_ATTN 16384
#define WP_FFN1 49152
#define WP_FFN2 65536
#define WP_TOTAL 81920
__device__ float g_wpack[WP_TOTAL];

// Wp[(kk*N + j)*2 + s] = W[2*kk + s][j]   (W is K x N row-major)
__global__ void pack_weights(const float* __restrict__ grp_wq,
                             const float* __restrict__ grp_wk,
                             const float* __restrict__ attn_w,
                             const float* __restrict__ ffn_w1,
                             const float* __restrict__ ffn_w2)
{
    int idx = blockIdx.x * 256 + threadIdx.x;
    if (idx >= WP_TOTAL) return;
    const float* src; int off; int N;
    if (idx < WP_GRPK)      { off = idx;            src = grp_wq + (off/4096)*4096; off &= 4095; N = 64; }
    else if (idx < WP_ATTN) { off = idx - WP_GRPK;  src = grp_wk + (off/4096)*4096; off &= 4095; N = 64; }
    else if (idx < WP_FFN1) { off = idx - WP_ATTN;  src = attn_w + (off/4096)*4096; off &= 4095; N = 64; }
    else if (idx < WP_FFN2) { off = idx - WP_FFN1;  src = ffn_w1 + (off/8192)*8192; off &= 8191; N = 128; }
    else                    { off = idx - WP_FFN2;  src = ffn_w2 + (off/8192)*8192; off &= 8191; N = 64; }
    int kk = off / (2*N); int r = off - kk*2*N; int j = r >> 1; int s = r & 1;
    g_wpack[idx] = src[(2*kk + s)*N + j];
}

struct Smem {
    float X [64*LD];
    float G [64*LD];
    float A [64*LD];
    float Bf[64*LD];
    float KV[2*64*LD];   // K ; V  (FFN hidden uses ld=LDF)
    float m0[64], dv[64], isd[64];
    float s1[64], s2[64];
    float q1[64], q2[64], S[64];
    float rw[64], cum[64], pooled[64], pmL[64], pmR[64];
    int   tok[64];
    float scal[8];
};

// Out[64 x 64] = A[64 x K] @ W + bias, W pre-packed k-interleaved with row width N.
// Inner loop: only 128-bit loads + FFMA2, zero pack movs.
template<int K, bool RELU, bool RES>
__device__ __forceinline__ void gemm64p(const float* __restrict__ Am, int lda,
                                        const float* __restrict__ Wp, int N,
                                        const float* __restrict__ bias,
                                        float* __restrict__ Out, int ldo, int tid)
{
    const int tx = tid & 15, ty = tid >> 4;
    const int i0 = ty * 4, j0 = tx * 4;
    ull acc[4][4];
    #pragma unroll
    for (int ii = 0; ii < 4; ii++)
        #pragma unroll
        for (int jj = 0; jj < 4; jj++) acc[ii][jj] = 0ull;

    #pragma unroll 4
    for (int kq = 0; kq < K/4; kq++) {
        ulonglong2 a[4];
        #pragma unroll
        for (int ii = 0; ii < 4; ii++)
            a[ii] = *(const ulonglong2*)(Am + (i0 + ii) * lda + 4 * kq);
        // kk0 = 2kq, kk1 = 2kq+1
        const float* wb0 = Wp + ((2*kq    ) * N + j0) * 2;
        const float* wb1 = Wp + ((2*kq + 1) * N + j0) * 2;
        ulonglong2 w00 = *(const ulonglong2*)(wb0);       // pairs for j0, j0+1 (kk0)
        ulonglong2 w01 = *(const ulonglong2*)(wb0 + 4);   // pairs for j0+2, j0+3
        ulonglong2 w10 = *(const ulonglong2*)(wb1);
        ulonglong2 w11 = *(const ulonglong2*)(wb1 + 4);
        #pragma unroll
        for (int ii = 0; ii < 4; ii++) {
            acc[ii][0] = ffma2(a[ii].x, w00.x, acc[ii][0]);
            acc[ii][1] = ffma2(a[ii].x, w00.y, acc[ii][1]);
            acc[ii][2] = ffma2(a[ii].x, w01.x, acc[ii][2]);
            acc[ii][3] = ffma2(a[ii].x, w01.y, acc[ii][3]);
            acc[ii][0] = ffma2(a[ii].y, w10.x, acc[ii][0]);
            acc[ii][1] = ffma2(a[ii].y, w10.y, acc[ii][1]);
            acc[ii][2] = ffma2(a[ii].y, w11.x, acc[ii][2]);
            acc[ii][3] = ffma2(a[ii].y, w11.y, acc[ii][3]);
        }
    }
    float4 bv = *(const float4*)(bias + j0);
    #pragma unroll
    for (int ii = 0; ii < 4; ii++) {
        float2 p0 = unpack2(acc[ii][0]);
        float2 p1 = unpack2(acc[ii][1]);
        float2 p2 = unpack2(acc[ii][2]);
        float2 p3 = unpack2(acc[ii][3]);
        float4 st;
        st.x = p0.x + p0.y + bv.x;
        st.y = p1.x + p1.y + bv.y;
        st.z = p2.x + p2.y + bv.z;
        st.w = p3.x + p3.y + bv.w;
        if (RELU) {
            st.x = fmaxf(st.x, 0.f); st.y = fmaxf(st.y, 0.f);
            st.z = fmaxf(st.z, 0.f); st.w = fmaxf(st.w, 0.f);
        }
        float* op = Out + (i0 + ii) * ldo + j0;
        if (RES) {
            float4 old = *(float4*)op;
            st.x += old.x; st.y += old.y; st.z += old.z; st.w += old.w;
        }
        *(float4*)op = st;
    }
}

// LayerNorm over 64, 4 threads per row.
__device__ __forceinline__ void layernorm(const float* __restrict__ Xm,
                                          const float* __restrict__ g,
                                          const float* __restrict__ bb,
                                          float* __restrict__ Out, int tid)
{
    const int r = tid >> 2, c0 = (tid & 3) * 16;
    const float4* xr = (const float4*)(Xm + r * LD + c0);
    float4 v0 = xr[0], v1 = xr[1], v2 = xr[2], v3 = xr[3];
    float s = v0.x+v0.y+v0.z+v0.w + v1.x+v1.y+v1.z+v1.w
            + v2.x+v2.y+v2.z+v2.w + v3.x+v3.y+v3.z+v3.w;
    s += __shfl_xor_sync(0xffffffffu, s, 1);
    s += __shfl_xor_sync(0xffffffffu, s, 2);
    const float mu = s * (1.f / 64.f);
    float var = 0.f;
    {
        float d;
        d = v0.x - mu; var += d*d;  d = v0.y - mu; var += d*d;
        d = v0.z - mu; var += d*d;  d = v0.w - mu; var += d*d;
        d = v1.x - mu; var += d*d;  d = v1.y - mu; var += d*d;
        d = v1.z - mu; var += d*d;  d = v1.w - mu; var += d*d;
        d = v2.x - mu; var += d*d;  d = v2.y - mu; var += d*d;
        d = v2.z - mu; var += d*d;  d = v2.w - mu; var += d*d;
        d = v3.x - mu; var += d*d;  d = v3.y - mu; var += d*d;
        d = v3.z - mu; var += d*d;  d = v3.w - mu; var += d*d;
    }
    var += __shfl_xor_sync(0xffffffffu, var, 1);
    var += __shfl_xor_sync(0xffffffffu, var, 2);
    const float rstd = rsqrtf(var * (1.f / 64.f) + 1e-6f);
    const float4* gp = (const float4*)(g + c0);
    const float4* bp = (const float4*)(bb + c0);
    float4* op = (float4*)(Out + r * LD + c0);
    float4 xv, gv, bv4, ov;
    #pragma unroll
    for (int q = 0; q < 4; q++) {
        xv = (q==0)?v0:((q==1)?v1:((q==2)?v2:v3));
        gv = gp[q]; bv4 = bp[q];
        ov.x = gv.x * (xv.x - mu) * rstd + bv4.x;
        ov.y = gv.y * (xv.y - mu) * rstd + bv4.y;
        ov.z = gv.z * (xv.z - mu) * rstd + bv4.z;
        ov.w = gv.w * (xv.w - mu) * rstd + bv4.w;
        op[q] = ov;
    }
}

__global__ __launch_bounds__(256, 2) void fsa_kernel(
    const int*   __restrict__ tok_g,
    const float* __restrict__ emb,
    const float* __restrict__ np_w,   const float* __restrict__ np_b,
    const float* __restrict__ grp_bq, const float* __restrict__ grp_bk,
    const float* __restrict__ grp_ln_g, const float* __restrict__ grp_ln_b,
    const float* __restrict__ attn_b,
    const float* __restrict__ ln1_g,  const float* __restrict__ ln1_b,
    const float* __restrict__ ln2_g,  const float* __restrict__ ln2_b,
    const float* __restrict__ ffn_b1, const float* __restrict__ ffn_b2,
    const float* __restrict__ enc_g,  const float* __restrict__ enc_b,
    const float* __restrict__ red_w,  const float* __restrict__ red_b,
    const float* __restrict__ opc_w,  const float* __restrict__ opc_b,
    const float* __restrict__ res_w,  const float* __restrict__ res_b,
    float* __restrict__ out, int out_size)
{
    extern __shared__ float smraw[];
    Smem& sm = *reinterpret_cast<Smem*>(smraw);
    const int b   = blockIdx.x;
    const int tid = threadIdx.x;

    // ---------------- token features ----------------
    if (tid < 64) {
        int t = tok_g[b * 64 + tid];
        sm.tok[tid] = t;
        sm.m0[tid]  = (t != 0) ? 1.f : 0.f;
        float isd   = (t >= 4 && t <= 13) ? 1.f : 0.f;
        sm.isd[tid] = isd;
        sm.dv[tid]  = ((float)t - 4.f) * isd;
    }
    __syncthreads();

    // ---------------- embed + numeric feats + PE ----------------
    {
        const int r = tid >> 2, c0 = (tid & 3) * 16;
        const int t = sm.tok[r];
        const float isd  = sm.isd[r];
        const float dvv  = sm.dv[r];
        const float isop = (t >= 14 && t <= 17) ? 1.f : 0.f;
        const float opt  = isop * ((float)t - 13.f);
        const float* erow = emb + t * 64;
        const float kfreq = (float)(-9.210340371976184 / 64.0);
        #pragma unroll 4
        for (int c = 0; c < 16; c++) {
            int cc = c0 + c;
            float base = erow[cc] * 8.f
                       + dvv  * np_w[cc]       + isd  * np_w[64 + cc]
                       + opt  * np_w[128 + cc] + isop * np_w[192 + cc]
                       + np_b[cc];
            float freq = expf((float)(cc & ~1) * kfreq);
            float ang  = (float)r * freq;
            float pe   = (cc & 1) ? cosf(ang) : sinf(ang);
            sm.X[r * LD + cc] = base + pe;
        }
    }
    __syncthreads();

    float* const Kb = sm.KV;
    float* const Vb = sm.KV + 64 * LD;

    // ================= layers =================
    #pragma unroll 1
    for (int l = 0; l < 2; l++) {
        // ---- group attention -> G ----
        layernorm(sm.X, grp_ln_g + l * 64, grp_ln_b + l * 64, sm.A, tid);
        __syncthreads();
        gemm64p<64,false,false>(sm.A, LD, g_wpack + WP_GRPQ + l*4096, 64, grp_bq + l * 64, sm.Bf, LD, tid);
        gemm64p<64,false,false>(sm.A, LD, g_wpack + WP_GRPK + l*4096, 64, grp_bk + l * 64, Kb,    LD, tid);
        __syncthreads();
        // tridiagonal scores
        if (tid < 63 || (tid >= 64 && tid < 127)) {
            int i   = (tid < 63) ? tid : (tid - 64);
            const ulonglong2* qp = (const ulonglong2*)(sm.Bf + ((tid < 63) ? i : i + 1) * LD);
            const ulonglong2* kp = (const ulonglong2*)(Kb   + ((tid < 63) ? i + 1 : i) * LD);
            ull acc = 0ull;
            #pragma unroll 4
            for (int m = 0; m < 16; m++) {
                ulonglong2 q4 = qp[m], k4 = kp[m];
                acc = ffma2(q4.x, k4.x, acc);
                acc = ffma2(q4.y, k4.y, acc);
            }
            float2 p = unpack2(acc);
            float sv = (p.x + p.y) * SGRP;
            if (tid < 63) sm.s1[i] = sv; else sm.s2[i] = sv;
        }
        __syncthreads();
        // fused neighbor softmax + symmetrize + prior mix
        if (tid < 64) {
            const int i = tid;
            const float m_i = sm.m0[i];
            bool vL = (i > 0)  && m_i > 0.f && sm.m0[i-1] > 0.f;
            bool vR = (i < 63) && m_i > 0.f && sm.m0[i+1] > 0.f;
            float pr_i, ps_i;
            if (!vL && !vR) { pr_i = 1.f/64.f; ps_i = 1.f/64.f; }
            else {
                float sL = vL ? sm.s2[i-1] : -3.4e38f;
                float sR = vR ? sm.s1[i]   : -3.4e38f;
                float m  = fmaxf(sL, sR);
                float eL = vL ? ex2f(sL - m) : 0.f;
                float eR = vR ? ex2f(sR - m) : 0.f;
                pr_i = eR / (eL + eR); ps_i = 0.f;
            }
            float nbd = sqrtf(ps_i * ps_i + 1e-9f);
            if (l > 0) { float pp = sm.G[i * LD + i]; nbd = pp + (1.f - pp) * nbd; }
            sm.q1[i] = nbd;
            if (i < 63) {
                const int i1 = i + 1;
                bool vL1 = m_i > 0.f && sm.m0[i1] > 0.f;
                bool vR1 = (i1 < 63) && sm.m0[i1] > 0.f && sm.m0[i1+1] > 0.f;
                float pl1;
                if (!vL1 && !vR1) pl1 = 1.f/64.f;
                else {
                    float sL = vL1 ? sm.s2[i]  : -3.4e38f;
                    float sR = vR1 ? sm.s1[i1] : -3.4e38f;
                    float m  = fmaxf(sL, sR);
                    float eL = vL1 ? ex2f(sL - m) : 0.f;
                    float eR = vR1 ? ex2f(sR - m) : 0.f;
                    pl1 = eL / (eL + eR);
                }
                float nbu = sqrtf(pr_i * pl1 + 1e-9f);
                if (l > 0) { float pp = sm.G[i * LD + i1]; nbu = pp + (1.f - pp) * nbu; }
                sm.q2[i] = lg2f_(nbu + 1e-9f);
            }
        }
        __syncthreads();
        if (tid == 0) {
            float a = 0.f; sm.S[0] = 0.f;
            for (int j = 1; j < 64; j++) { a += sm.q2[j-1]; sm.S[j] = a; }
        }
        __syncthreads();
        for (int t = tid; t < 4096; t += 256) {
            int i = t >> 6, j = t & 63;
            float v;
            if (i == j) v = sm.q1[i];
            else {
                int lo = (i < j) ? i : j, hi = (i < j) ? j : i;
                v = ex2f(sm.S[hi] - sm.S[lo]) + 1e-9f;
            }
            sm.G[i * LD + j] = v;
        }
        __syncthreads();

        // ---- multi-head attention weighted by g ----
        layernorm(sm.X, ln1_g + l * 64, ln1_b + l * 64, sm.A, tid);
        __syncthreads();
        gemm64p<64,false,false>(sm.A, LD, g_wpack + WP_ATTN + (l*4+0)*4096, 64, attn_b + (l*4+0)*64, sm.Bf, LD, tid);
        gemm64p<64,false,false>(sm.A, LD, g_wpack + WP_ATTN + (l*4+1)*4096, 64, attn_b + (l*4+1)*64, Kb,    LD, tid);
        gemm64p<64,false,false>(sm.A, LD, g_wpack + WP_ATTN + (l*4+2)*4096, 64, attn_b + (l*4+2)*64, Vb,    LD, tid);
        __syncthreads();
        #pragma unroll 1
        for (int h = 0; h < 4; h++) {
            {   // scores + softmax * g -> sm.A
                const int r = tid >> 2, seg = tid & 3;
                const ulonglong2* qp = (const ulonglong2*)(sm.Bf + r * LD + h * 16);
                ulonglong2 qA = qp[0], qB = qp[1], qC = qp[2], qD = qp[3];
                float sc[16]; float mx = -3.4e38f;
                #pragma unroll 4
                for (int jj = 0; jj < 16; jj++) {
                    int j = 4 * jj + seg;
                    float sv;
                    if (sm.m0[j] > 0.f) {
                        const ulonglong2* kp = (const ulonglong2*)(Kb + j * LD + h * 16);
                        ulonglong2 kA = kp[0], kB = kp[1], kC = kp[2], kD = kp[3];
                        ull acc = 0ull;
                        acc = ffma2(qA.x, kA.x, acc);
                        acc = ffma2(qA.y, kA.y, acc);
                        acc = ffma2(qB.x, kB.x, acc);
                        acc = ffma2(qB.y, kB.y, acc);
                        acc = ffma2(qC.x, kC.x, acc);
                        acc = ffma2(qC.y, kC.y, acc);
                        acc = ffma2(qD.x, kD.x, acc);
                        acc = ffma2(qD.y, kD.y, acc);
                        float2 p = unpack2(acc);
                        sv = (p.x + p.y) * SATT;
                    } else sv = -1e9f;
                    sc[jj] = sv; mx = fmaxf(mx, sv);
                }
                mx = fmaxf(mx, __shfl_xor_sync(0xffffffffu, mx, 1));
                mx = fmaxf(mx, __shfl_xor_sync(0xffffffffu, mx, 2));
                float sum = 0.f;
                #pragma unroll
                for (int jj = 0; jj < 16; jj++) { float e = ex2f(sc[jj] - mx); sc[jj] = e; sum += e; }
                sum += __shfl_xor_sync(0xffffffffu, sum, 1);
                sum += __shfl_xor_sync(0xffffffffu, sum, 2);
                const float inv = 1.f / sum;
                #pragma unroll
                for (int jj = 0; jj < 16; jj++) {
                    int j = 4 * jj + seg;
                    sm.A[r * LD + j] = sc[jj] * inv * sm.G[r * LD + j];
                }
            }
            __syncthreads();
            {   // O_h = P @ V_h
                const int i = tid >> 2, c = tid & 3;
                ull o01 = 0ull, o23 = 0ull;
                const float* vbase = Vb + h * 16 + c * 4;
                const float* prow  = sm.A + i * LD;
                #pragma unroll 4
                for (int jj = 0; jj < 16; jj++) {
                    float4 p4 = *(const float4*)(prow + 4 * jj);
                    {
                        ulonglong2 v = *(const ulonglong2*)(vbase + (4 * jj + 0) * LD);
                        ull pb = pack2(p4.x, p4.x);
                        o01 = ffma2(pb, v.x, o01);
                        o23 = ffma2(pb, v.y, o23);
                    }
                    {
                        ulonglong2 v = *(const ulonglong2*)(vbase + (4 * jj + 1) * LD);
                        ull pb = pack2(p4.y, p4.y);
                        o01 = ffma2(pb, v.x, o01);
                        o23 = ffma2(pb, v.y, o23);
                    }
                    {
                        ulonglong2 v = *(const ulonglong2*)(vbase + (4 * jj + 2) * LD);
                        ull pb = pack2(p4.z, p4.z);
                        o01 = ffma2(pb, v.x, o01);
                        o23 = ffma2(pb, v.y, o23);
                    }
                    {
                        ulonglong2 v = *(const ulonglong2*)(vbase + (4 * jj + 3) * LD);
                        ull pb = pack2(p4.w, p4.w);
                        o01 = ffma2(pb, v.x, o01);
                        o23 = ffma2(pb, v.y, o23);
                    }
                }
                float2 a01 = unpack2(o01), a23 = unpack2(o23);
                float4 st; st.x = a01.x; st.y = a01.y; st.z = a23.x; st.w = a23.y;
                *(float4*)(sm.Bf + i * LD + h * 16 + c * 4) = st;
            }
            __syncthreads();
        }
        // x += O @ Wo + bo
        gemm64p<64,false,true>(sm.Bf, LD, g_wpack + WP_ATTN + (l*4+3)*4096, 64, attn_b + (l*4+3)*64, sm.X, LD, tid);
        __syncthreads();

        // ---- FFN ----
        layernorm(sm.X, ln2_g + l * 64, ln2_b + l * 64, sm.A, tid);
        __syncthreads();
        gemm64p<64,true,false>(sm.A, LD, g_wpack + WP_FFN1 + l*8192,       128, ffn_b1 + l * 128,      sm.KV,      LDF, tid);
        gemm64p<64,true,false>(sm.A, LD, g_wpack + WP_FFN1 + l*8192 + 128, 128, ffn_b1 + l * 128 + 64, sm.KV + 64, LDF, tid);
        __syncthreads();
        gemm64p<128,false,true>(sm.KV, LDF, g_wpack + WP_FFN2 + l*8192, 64, ffn_b2 + l * 64, sm.X, LD, tid);
        __syncthreads();
    }

    // ================= readout =================
    layernorm(sm.X, enc_g, enc_b, sm.A, tid);
    __syncthreads();
    if (tid < 64) {
        const ulonglong2* xr = (const ulonglong2*)(sm.A + tid * LD);
        const ulonglong2* wr = (const ulonglong2*)red_w;
        ull acc = 0ull;
        #pragma unroll 4
        for (int m = 0; m < 16; m++) {
            ulonglong2 x4 = xr[m], w4 = wr[m];
            acc = ffma2(x4.x, w4.x, acc);
            acc = ffma2(x4.y, w4.y, acc);
        }
        float2 p = unpack2(acc);
        float s = p.x + p.y + red_b[0];
        s += (1.f - sm.m0[tid]) * (-1e9f);
        sm.s1[tid] = s;
    }
    __syncthreads();
    if (tid == 0) {
        float m = -3.4e38f;
        for (int i = 0; i < 64; i++) m = fmaxf(m, sm.s1[i]);
        sm.scal[0] = m;
    }
    __syncthreads();
    if (tid < 64) sm.s2[tid] = ex2f((sm.s1[tid] - sm.scal[0]) * LOG2E);
    __syncthreads();
    if (tid == 0) {
        float Z = 0.f;
        for (int i = 0; i < 64; i++) Z += sm.s2[i];
        sm.scal[1] = Z;
    }
    __syncthreads();
    if (tid < 64) sm.rw[tid] = sm.s2[tid] / sm.scal[1];
    __syncthreads();
    if (tid == 0) {
        float c = 0.f;
        for (int i = 0; i < 64; i++) { c += sm.rw[i]; sm.cum[i] = c; }
    }
    __syncthreads();
    if (tid < 64) {
        sm.pmL[tid] = (1.f - sm.cum[tid]) * sm.isd[tid];
        sm.pmR[tid] = (sm.cum[tid] - sm.rw[tid]) * sm.isd[tid];
    }
    if (tid >= 64 && tid < 128) {
        int h = tid - 64;
        float p = 0.f;
        #pragma unroll 8
        for (int ll = 0; ll < 64; ll++) p = fmaf(sm.A[ll * LD + h], sm.rw[ll], p);
        sm.pooled[h] = p;
    }
    __syncthreads();
    if (tid == 0) {
        float lv, rv;
        {
            float tot = 0.f; for (int i = 0; i < 64; i++) tot += sm.pmL[i];
            float run = 0.f, acc = 0.f;
            for (int i = 0; i < 64; i++) {
                float smk = sm.pmL[i];
                run += smk;
                float w = ex2f((tot - run) * smk * LOG2_10) * smk;
                acc = fmaf(sm.dv[i], w, acc);
            }
            lv = acc;
        }
        {
            float tot = 0.f; for (int i = 0; i < 64; i++) tot += sm.pmR[i];
            float run = 0.f, acc = 0.f;
            for (int i = 0; i < 64; i++) {
                float smk = sm.pmR[i];
                run += smk;
                float w = ex2f((tot - run) * smk * LOG2_10) * smk;
                acc = fmaf(sm.dv[i], w, acc);
            }
            rv = acc;
        }
        float lg[4];
        for (int o = 0; o < 4; o++) {
            float a = opc_b[o];
            for (int h = 0; h < 64; h++) a = fmaf(sm.pooled[h], opc_w[h * 4 + o], a);
            lg[o] = a;
        }
        int op = 0; float bm = lg[0];
        for (int o = 1; o < 4; o++) if (lg[o] > bm) { bm = lg[o]; op = o; }
        float result, valid = 1.f;
        if      (op == 0) result = lv + rv;
        else if (op == 1) result = lv - rv;
        else if (op == 2) result = lv * rv;
        else {
            bool bad = fabsf(rv) < 1e-6f;
            result = bad ? 0.f : lv / rv;
            valid  = bad ? 0.f : 1.f;
        }
        float sgn = (result > 0.f) ? 1.f : ((result < 0.f) ? -1.f : 0.f);
        float rc  = sgn * log1pf(fabsf(result));
        sm.scal[2] = result; sm.scal[3] = valid; sm.scal[4] = rc;
        sm.scal[5] = lv;     sm.scal[6] = rv;
        sm.s1[0] = lg[0]; sm.s1[1] = lg[1]; sm.s1[2] = lg[2]; sm.s1[3] = lg[3];
    }
    __syncthreads();

    const bool full = (out_size >= 136 * NB);
    if (full) {
        if (tid == 0) {
            out[b]           = sm.scal[2];
            out[65*NB + b]   = sm.scal[3];
            out[66*NB + b]   = sm.scal[5];
            out[67*NB + b]   = sm.scal[6];
            #pragma unroll
            for (int o = 0; o < 4; o++) out[68*NB + b*4 + o] = sm.s1[o];
        }
        if (tid < 64) {
            float rc = sm.scal[4], valid = sm.scal[3];
            out[NB + b*64 + tid]    = rc * res_w[tid] + valid * res_w[64 + tid] + res_b[tid];
            out[72*NB + b*64 + tid] = sm.rw[tid];
        }
    } else {
        if (tid == 0) out[b] = sm.scal[2];
    }
}

extern "C" void kernel_launch(void* const* d_in, const int* in_sizes, int n_in,
                              void* d_out, int out_size)
{
    // 1) pack weights into k-interleaved layout (graph-capturable, deterministic)
    pack_weights<<<(WP_TOTAL + 255) / 256, 256>>>(
        (const float*)d_in[4],   // grp_wq
        (const float*)d_in[6],   // grp_wk
        (const float*)d_in[10],  // attn_w
        (const float*)d_in[16],  // ffn_w1
        (const float*)d_in[18]); // ffn_w2

    // 2) main fused kernel
    const size_t shmem = sizeof(Smem);
    cudaFuncSetAttribute(fsa_kernel, cudaFuncAttributeMaxDynamicSharedMemorySize, (int)shmem);
    fsa_kernel<<<NB, 256, shmem>>>(
        (const int*)  d_in[0],   // token_ids
        (const float*)d_in[1],   // emb
        (const float*)d_in[2],  (const float*)d_in[3],    // np_w, np_b
        (const float*)d_in[5],  (const float*)d_in[7],    // grp_bq, grp_bk
        (const float*)d_in[8],  (const float*)d_in[9],    // grp_ln_g, grp_ln_b
        (const float*)d_in[11],                            // attn_b
        (const float*)d_in[12], (const float*)d_in[13],   // ln1_g, ln1_b
        (const float*)d_in[14], (const float*)d_in[15],   // ln2_g, ln2_b
        (const float*)d_in[17], (const float*)d_in[19],   // ffn_b1, ffn_b2
        (const float*)d_in[20], (const float*)d_in[21],   // enc_g, enc_b
        (const float*)d_in[22], (const float*)d_in[23],   // red_w, red_b
        (const float*)d_in[24], (const float*)d_in[25],   // opc_w, opc_b
        (const float*)d_in[26], (const float*)d_in[27],   // res_w, res_b
        (float*)d_out, out_size);
}